// round 5
// baseline (speedup 1.0000x reference)
#include <cuda_runtime.h>
#include <cstdint>

// Problem: input (512, 2048, 7, 7) fp32 -> per row of 49: mean of top-4.
// Output: (512, 2048, 1, 1) = 1,048,576 floats.
//
// R4: same double-buffered cp.async persistent pipeline as R3, with:
//  - grid = 296 = 2 x 148 SMs exactly (R3's 304 left 8 straggler blocks
//    serializing behind the full first wave)
//  - 512 threads/block, 2 threads per row: each thread top-4's half a row
//    (sort4 + bitonic merges), then lane-pairs merge via shfl_xor(1).
//    Same smem (2 x 50KB), double the warps (occ 25% -> 50%) and half the
//    per-tile compute critical path -> pipeline bubbles covered.

#define THREADS      512
#define TILE_ROWS    256
#define ROW_LEN      49
#define TILE_FLOATS  (TILE_ROWS * ROW_LEN)   // 12544
#define TILE_VEC4    (TILE_FLOATS / 4)       // 3136
#define TILE_BYTES   (TILE_FLOATS * 4)       // 50176
#define GRID_BLOCKS  296

__device__ __forceinline__ void ce(float& x, float& y) {
    float hi = fmaxf(x, y);
    float lo = fminf(x, y);
    x = hi; y = lo;
}

__device__ __forceinline__ void sort4(float& a, float& b, float& c, float& d) {
    ce(a, b); ce(c, d); ce(a, c); ce(b, d); ce(b, c);
}

// merge sorted-desc acc (t) with sorted-desc chunk (c): top-4 of the 8
__device__ __forceinline__ void merge4(float& t0, float& t1, float& t2, float& t3,
                                       float c0, float c1, float c2, float c3) {
    float m0 = fmaxf(t0, c3);
    float m1 = fmaxf(t1, c2);
    float m2 = fmaxf(t2, c1);
    float m3 = fmaxf(t3, c0);
    ce(m0, m2); ce(m1, m3); ce(m0, m1); ce(m2, m3);
    t0 = m0; t1 = m1; t2 = m2; t3 = m3;
}

__device__ __forceinline__ void cp_async16(uint32_t smem_dst, const float4* gmem_src) {
    asm volatile("cp.async.cg.shared.global [%0], [%1], 16;\n"
                 :: "r"(smem_dst), "l"(gmem_src));
}

__device__ __forceinline__ void cp_commit() {
    asm volatile("cp.async.commit_group;\n" ::: "memory");
}

template <int N>
__device__ __forceinline__ void cp_wait() {
    asm volatile("cp.async.wait_group %0;\n" :: "n"(N) : "memory");
}

__global__ __launch_bounds__(THREADS)
void apool_topk4_kernel(const float* __restrict__ in, float* __restrict__ out,
                        int ntiles) {
    extern __shared__ float s[];   // 2 * TILE_FLOATS

    const int tid  = threadIdx.x;
    const int row  = tid >> 1;       // 0..255
    const int half = tid & 1;        // 0: elems 0..23, 1: elems 24..48
    const uint32_t s_base = (uint32_t)__cvta_generic_to_shared(s);

    // ---- Prologue: start loading first tile into buffer 0 ----
    int t = blockIdx.x;
    if (t < ntiles) {
        const float4* src = reinterpret_cast<const float4*>(in) +
                            (long long)t * TILE_VEC4;
        #pragma unroll 4
        for (int i = tid; i < TILE_VEC4; i += THREADS)
            cp_async16(s_base + (uint32_t)i * 16u, src + i);
    }
    cp_commit();

    int buf = 0;
    for (; t < ntiles; t += GRID_BLOCKS) {
        const int tn = t + GRID_BLOCKS;
        if (tn < ntiles) {
            const uint32_t dst = s_base + (uint32_t)(buf ^ 1) * (uint32_t)TILE_BYTES;
            const float4* src = reinterpret_cast<const float4*>(in) +
                                (long long)tn * TILE_VEC4;
            #pragma unroll 4
            for (int i = tid; i < TILE_VEC4; i += THREADS)
                cp_async16(dst + (uint32_t)i * 16u, src + i);
            cp_commit();
            cp_wait<1>();   // current tile complete; next stays in flight
        } else {
            cp_commit();
            cp_wait<0>();
        }
        __syncthreads();

        // ---- Compute: 2 threads per row ----
        const float* half_row = s + buf * TILE_FLOATS + row * ROW_LEN + half * 24;

        float t0 = half_row[0], t1 = half_row[1], t2 = half_row[2], t3 = half_row[3];
        sort4(t0, t1, t2, t3);

        #pragma unroll
        for (int k = 1; k < 6; k++) {
            float c0 = half_row[4 * k + 0];
            float c1 = half_row[4 * k + 1];
            float c2 = half_row[4 * k + 2];
            float c3 = half_row[4 * k + 3];
            sort4(c0, c1, c2, c3);
            merge4(t0, t1, t2, t3, c0, c1, c2, c3);
        }
        if (half) {
            // odd thread also owns element 48 (its 25th)
            float e = half_row[24];
            t3 = fmaxf(t3, e);
            ce(t2, t3); ce(t1, t2); ce(t0, t1);
        }

        // ---- Pair merge across the two half-row threads ----
        float p0 = __shfl_xor_sync(0xFFFFFFFFu, t0, 1);
        float p1 = __shfl_xor_sync(0xFFFFFFFFu, t1, 1);
        float p2 = __shfl_xor_sync(0xFFFFFFFFu, t2, 1);
        float p3 = __shfl_xor_sync(0xFFFFFFFFu, t3, 1);
        merge4(t0, t1, t2, t3, p0, p1, p2, p3);

        if (half == 0)
            out[(long long)t * TILE_ROWS + row] = (t0 + t1 + t2 + t3) * 0.25f;

        buf ^= 1;
        __syncthreads();   // everyone done reading old buffer before overwrite
    }
}

extern "C" void kernel_launch(void* const* d_in, const int* in_sizes, int n_in,
                              void* d_out, int out_size) {
    const float* in = (const float*)d_in[0];
    float* out = (float*)d_out;

    const int rows = out_size;                 // 1,048,576
    const int ntiles = rows / TILE_ROWS;       // 4096, divides exactly
    const int smem = 2 * TILE_BYTES;           // 100,352 B

    cudaFuncSetAttribute(apool_topk4_kernel,
                         cudaFuncAttributeMaxDynamicSharedMemorySize, smem);
    apool_topk4_kernel<<<GRID_BLOCKS, THREADS, smem>>>(in, out, ntiles);
}

// round 7
// speedup vs baseline: 1.2817x; 1.2817x over previous
#include <cuda_runtime.h>
#include <cstdint>

// Problem: input (512, 2048, 7, 7) fp32 -> per row of 49: mean of top-4.
// Output: (512, 2048, 1, 1) = 1,048,576 floats.
//
// R5: R3 pipeline (persistent, double-buffered, 256 thr, 1 row/thread) but
// the per-tile copy is ONE cp.async.bulk (TMA bulk DMA, 50,176 B) instead of
// 3136 cp.async.cg ops. Completion via mbarrier complete_tx; warps spend all
// their time on the top-4 math while the async engine streams the next tile.

#define THREADS      256
#define TILE_ROWS    256
#define ROW_LEN      49
#define TILE_FLOATS  (TILE_ROWS * ROW_LEN)   // 12544
#define TILE_BYTES   (TILE_FLOATS * 4)       // 50176 (16B-multiple: ok for bulk)
#define GRID_BLOCKS  296                     // 2 CTAs x 148 SMs exactly

__device__ __forceinline__ void ce(float& x, float& y) {
    float hi = fmaxf(x, y);
    float lo = fminf(x, y);
    x = hi; y = lo;
}

__device__ __forceinline__ void sort4(float& a, float& b, float& c, float& d) {
    ce(a, b); ce(c, d); ce(a, c); ce(b, d); ce(b, c);
}

__device__ __forceinline__ void merge4(float& t0, float& t1, float& t2, float& t3,
                                       float c0, float c1, float c2, float c3) {
    float m0 = fmaxf(t0, c3);
    float m1 = fmaxf(t1, c2);
    float m2 = fmaxf(t2, c1);
    float m3 = fmaxf(t3, c0);
    ce(m0, m2); ce(m1, m3); ce(m0, m1); ce(m2, m3);
    t0 = m0; t1 = m1; t2 = m2; t3 = m3;
}

__device__ __forceinline__ void mbar_init(uint32_t a, uint32_t cnt) {
    asm volatile("mbarrier.init.shared.b64 [%0], %1;" :: "r"(a), "r"(cnt) : "memory");
}

__device__ __forceinline__ void mbar_expect_tx(uint32_t a, uint32_t bytes) {
    asm volatile("mbarrier.arrive.expect_tx.shared.b64 _, [%0], %1;"
                 :: "r"(a), "r"(bytes) : "memory");
}

__device__ __forceinline__ void mbar_wait(uint32_t a, uint32_t parity) {
    asm volatile(
        "{\n\t"
        ".reg .pred p;\n\t"
        "WAIT_%=:\n\t"
        "mbarrier.try_wait.parity.shared.b64 p, [%0], %1;\n\t"
        "@!p bra WAIT_%=;\n\t"
        "}"
        :: "r"(a), "r"(parity) : "memory");
}

__device__ __forceinline__ void bulk_copy(uint32_t smem_dst, const void* gmem_src,
                                          uint32_t bytes, uint32_t mbar) {
    asm volatile(
        "cp.async.bulk.shared::cta.global.mbarrier::complete_tx::bytes "
        "[%0], [%1], %2, [%3];"
        :: "r"(smem_dst), "l"(gmem_src), "r"(bytes), "r"(mbar) : "memory");
}

__global__ __launch_bounds__(THREADS)
void apool_topk4_kernel(const float* __restrict__ in, float* __restrict__ out,
                        int ntiles) {
    extern __shared__ float s[];                 // 2 * TILE_FLOATS
    __shared__ __align__(8) uint64_t mbar_s[2];

    const int tid = threadIdx.x;
    const uint32_t s_base = (uint32_t)__cvta_generic_to_shared(s);
    const uint32_t mb[2] = { (uint32_t)__cvta_generic_to_shared(&mbar_s[0]),
                             (uint32_t)__cvta_generic_to_shared(&mbar_s[1]) };

    if (tid == 0) {
        mbar_init(mb[0], 1);
        mbar_init(mb[1], 1);
        asm volatile("fence.proxy.async.shared::cta;" ::: "memory");
    }
    __syncthreads();

    // ---- Prologue: issue first tile into buffer 0 ----
    int t = blockIdx.x;
    if (t < ntiles && tid == 0) {
        mbar_expect_tx(mb[0], TILE_BYTES);
        bulk_copy(s_base, in + (long long)t * TILE_FLOATS, TILE_BYTES, mb[0]);
    }

    int it = 0;
    for (; t < ntiles; t += GRID_BLOCKS, it++) {
        const int buf = it & 1;
        const uint32_t par = (uint32_t)(it >> 1) & 1u;

        // issue next tile into the other buffer (safe: __syncthreads at the
        // end of the previous iteration guarantees everyone finished it)
        const int tn = t + GRID_BLOCKS;
        if (tn < ntiles && tid == 0) {
            const int nb = buf ^ 1;
            mbar_expect_tx(mb[nb], TILE_BYTES);
            bulk_copy(s_base + (uint32_t)nb * (uint32_t)TILE_BYTES,
                      in + (long long)tn * TILE_FLOATS, TILE_BYTES, mb[nb]);
        }

        // wait for current tile's DMA completion
        mbar_wait(mb[buf], par);

        // ---- Compute: one row per thread (stride 49 -> conflict-free) ----
        const float* row = s + buf * TILE_FLOATS + tid * ROW_LEN;

        float t0 = row[0], t1 = row[1], t2 = row[2], t3 = row[3];
        sort4(t0, t1, t2, t3);

        #pragma unroll
        for (int k = 1; k < 12; k++) {
            float c0 = row[4 * k + 0];
            float c1 = row[4 * k + 1];
            float c2 = row[4 * k + 2];
            float c3 = row[4 * k + 3];
            sort4(c0, c1, c2, c3);
            merge4(t0, t1, t2, t3, c0, c1, c2, c3);
        }
        float e = row[48];
        t3 = fmaxf(t3, e);
        ce(t2, t3); ce(t1, t2); ce(t0, t1);

        out[(long long)t * TILE_ROWS + tid] = (t0 + t1 + t2 + t3) * 0.25f;

        __syncthreads();   // all done reading buf before it gets overwritten
    }
}

extern "C" void kernel_launch(void* const* d_in, const int* in_sizes, int n_in,
                              void* d_out, int out_size) {
    const float* in = (const float*)d_in[0];
    float* out = (float*)d_out;

    const int rows = out_size;                 // 1,048,576
    const int ntiles = rows / TILE_ROWS;       // 4096, divides exactly
    const int smem = 2 * TILE_BYTES;           // 100,352 B

    cudaFuncSetAttribute(apool_topk4_kernel,
                         cudaFuncAttributeMaxDynamicSharedMemorySize, smem);
    apool_topk4_kernel<<<GRID_BLOCKS, THREADS, smem>>>(in, out, ntiles);
}